// round 5
// baseline (speedup 1.0000x reference)
#include <cuda_runtime.h>
#include <math.h>
#include <stdint.h>

#define HD 32
#define MAXN 10000
#define CAP 256   // max in-degree supported (E/N = 32 mean, Poisson tail << 256)

// Scratch (device globals — no allocation allowed)
__device__ float g_z[MAXN * HD];
__device__ float g_u[MAXN * HD];
__device__ float g_v[MAXN * HD];
__device__ float g_pa[MAXN];
__device__ float g_pb[MAXN];
__device__ float g_hsum[HD];
__device__ int   g_cnt[MAXN];      // static zero-init for first call; reset by k_rowfill each call
__device__ int   g_list[MAXN * CAP];

// ---------------------------------------------------------------------------
// Kernel A: blocks [0, EB) build the per-dest edge list;
//           blocks [EB, EB+NB) run the encoder (warp per node).
//           block 0 also zeroes g_hsum.
// ---------------------------------------------------------------------------
__global__ void k_build_enc(const int* __restrict__ dests,
                            const float* __restrict__ x, const float* __restrict__ h,
                            const float* __restrict__ W_enc, const float* __restrict__ b_enc,
                            const float* __restrict__ W_msg, int N, int E, int EB) {
    int tid = threadIdx.x;
    if ((int)blockIdx.x < EB) {
        // ---- build part: thread per edge ----
        if (blockIdx.x == 0 && tid < HD) g_hsum[tid] = 0.0f;
        int e = blockIdx.x * blockDim.x + tid;
        if (e < E) {
            int d = dests[e];
            int slot = atomicAdd(&g_cnt[d], 1);
            if (slot < CAP) g_list[d * CAP + slot] = e;
        }
        return;
    }

    // ---- encoder part: warp per node ----
    __shared__ float sWe[33 * HD];
    __shared__ float sWm[64 * HD];
    for (int i = tid; i < 33 * HD; i += blockDim.x) sWe[i] = W_enc[i];
    for (int i = tid; i < 64 * HD; i += blockDim.x) sWm[i] = W_msg[i];
    __syncthreads();

    int lane = tid & 31;
    int node = (int)(((blockIdx.x - EB) * (size_t)blockDim.x + tid) >> 5);
    if (node >= N) return;

    float xn = x[node];
    float hl = h[node * HD + lane];
    float z0 = fmaf(xn, sWe[lane], b_enc[lane]);
    float z1 = 0.0f;
#pragma unroll
    for (int k = 0; k < HD; k += 2) {
        float hk0 = __shfl_sync(0xffffffffu, hl, k);
        float hk1 = __shfl_sync(0xffffffffu, hl, k + 1);
        z0 = fmaf(hk0, sWe[(1 + k) * HD + lane], z0);
        z1 = fmaf(hk1, sWe[(2 + k) * HD + lane], z1);
    }
    float z = z0 + z1;
    g_z[node * HD + lane] = z;

    float u = 0.0f, v = 0.0f;
#pragma unroll
    for (int k = 0; k < HD; k++) {
        float zk = __shfl_sync(0xffffffffu, z, k);
        u = fmaf(zk, sWm[k * HD + lane], u);
        v = fmaf(zk, sWm[(HD + k) * HD + lane], v);
    }
    g_u[node * HD + lane] = u;
    g_v[node * HD + lane] = v;
}

// ---------------------------------------------------------------------------
// Kernel B: segment-max (atomic-free, lane-parallel edge loads, 4x-unrolled
// gathers) + update + decode + pred scalars + hsum. Warp per node.
// ---------------------------------------------------------------------------
__global__ void k_update(const int* __restrict__ sources, const float* __restrict__ weights,
                         const float* __restrict__ W_msg, const float* __restrict__ b_msg,
                         const float* __restrict__ W_upd, const float* __restrict__ b_upd,
                         const float* __restrict__ W_dec, const float* __restrict__ b_dec,
                         const float* __restrict__ W_pred,
                         float* __restrict__ out_y, float* __restrict__ out_h, int N) {
    __shared__ float sWu[64 * HD];
    __shared__ float red[8][HD];
    int tid = threadIdx.x;
    for (int i = tid; i < 64 * HD; i += blockDim.x) sWu[i] = W_upd[i];
    __syncthreads();

    int lane = tid & 31;
    int wip  = tid >> 5;
    int node = (int)((blockIdx.x * (size_t)blockDim.x + tid) >> 5);
    bool act = node < N;
    float hn = 0.0f;

    if (act) {
        float cw = W_msg[64 * HD + lane];
        int cnt = min(g_cnt[node], CAP);
        const int* lst = &g_list[node * CAP];

        float mraw = __int_as_float(0xFF800000);  // -inf
        for (int base = 0; base < cnt; base += 32) {
            int nrem = min(32, cnt - base);
            int   myS = 0;
            float myW = 0.0f;
            if (lane < nrem) {
                int e = lst[base + lane];     // coalesced
                myS = sources[e];
                myW = weights[e];
            }
            int k = 0;
            for (; k + 4 <= nrem; k += 4) {
                int   s0 = __shfl_sync(0xffffffffu, myS, k);
                int   s1 = __shfl_sync(0xffffffffu, myS, k + 1);
                int   s2 = __shfl_sync(0xffffffffu, myS, k + 2);
                int   s3 = __shfl_sync(0xffffffffu, myS, k + 3);
                float w0 = __shfl_sync(0xffffffffu, myW, k);
                float w1 = __shfl_sync(0xffffffffu, myW, k + 1);
                float w2 = __shfl_sync(0xffffffffu, myW, k + 2);
                float w3 = __shfl_sync(0xffffffffu, myW, k + 3);
                float v0 = g_v[s0 * HD + lane];   // 4 independent gathers -> MLP 4
                float v1 = g_v[s1 * HD + lane];
                float v2 = g_v[s2 * HD + lane];
                float v3 = g_v[s3 * HD + lane];
                float a = fmaxf(fmaf(w0, cw, v0), fmaf(w1, cw, v1));
                float b = fmaxf(fmaf(w2, cw, v2), fmaf(w3, cw, v3));
                mraw = fmaxf(mraw, fmaxf(a, b));
            }
            for (; k < nrem; k++) {
                int   sk = __shfl_sync(0xffffffffu, myS, k);
                float wk = __shfl_sync(0xffffffffu, myW, k);
                mraw = fmaxf(mraw, fmaf(wk, cw, g_v[sk * HD + lane]));
            }
        }

        float z = g_z[node * HD + lane];
        float m = (cnt == 0) ? 0.0f
                             : (g_u[node * HD + lane] + b_msg[lane] + mraw);

        float h0 = b_upd[lane], h1 = 0.0f;
#pragma unroll
        for (int k = 0; k < HD; k++) {
            float zk = __shfl_sync(0xffffffffu, z, k);
            float mk = __shfl_sync(0xffffffffu, m, k);
            h0 = fmaf(zk, sWu[k * HD + lane], h0);
            h1 = fmaf(mk, sWu[(HD + k) * HD + lane], h1);
        }
        hn = h0 + h1;
        out_h[node * HD + lane] = hn;

        float ry = fmaf(z, W_dec[lane], hn * W_dec[HD + lane]);
        float ra = hn * W_pred[lane];
        float rb = hn * W_pred[HD + lane];
#pragma unroll
        for (int o = 16; o > 0; o >>= 1) {
            ry += __shfl_xor_sync(0xffffffffu, ry, o);
            ra += __shfl_xor_sync(0xffffffffu, ra, o);
            rb += __shfl_xor_sync(0xffffffffu, rb, o);
        }
        if (lane == 0) {
            out_y[node] = ry + b_dec[0];
            g_pa[node] = ra;
            g_pb[node] = rb;
        }
    }

    red[wip][lane] = act ? hn : 0.0f;
    __syncthreads();
    if (wip == 0) {
        float s = red[0][lane];
#pragma unroll
        for (int j = 1; j < 8; j++) s += red[j][lane];
        atomicAdd(&g_hsum[lane], s);
    }
}

// ---------------------------------------------------------------------------
// Kernel C: fused row fill + edge-score overwrite + termination head +
// g_cnt reset for the next replay. Grid-stride over rows (8 blocks/SM).
// Each row of p is written exactly once.
// ---------------------------------------------------------------------------
__global__ void k_rowfill(const int* __restrict__ sources, const float* __restrict__ weights,
                          const float* __restrict__ W_pred, const float* __restrict__ b_pred,
                          const float* __restrict__ W_term, const float* __restrict__ b_term,
                          float* __restrict__ p, float* __restrict__ out_t, int N) {
    int tid = threadIdx.x;

    // termination head (block 0, warp 0) — g_hsum is complete after k_update
    if (blockIdx.x == 0 && tid < 32) {
        float v = (g_hsum[tid] / (float)N) * W_term[tid];
#pragma unroll
        for (int o = 16; o > 0; o >>= 1) v += __shfl_xor_sync(0xffffffffu, v, o);
        if (tid == 0) out_t[0] = v + b_term[0];
    }

    float c  = W_pred[64];
    float b0 = b_pred[0];
    const float4 val = make_float4(-1e9f, -1e9f, -1e9f, -1e9f);
    int n4 = N >> 2;
    int nrem_start = n4 << 2;

    for (int d = blockIdx.x; d < N; d += gridDim.x) {
        float* row = p + (size_t)d * N;
        float4* row4 = (float4*)row;
        for (int i = tid; i < n4; i += blockDim.x) row4[i] = val;
        for (int i = nrem_start + tid; i < N; i += blockDim.x) row[i] = -1e9f;
        __syncthreads();   // row fully filled before edge overwrites

        int cnt = min(g_cnt[d], CAP);
        if (tid < cnt) {
            float pa = g_pa[d];
            for (int i = tid; i < cnt; i += blockDim.x) {
                int e = g_list[d * CAP + i];
                int s = sources[e];
                row[s] = pa + g_pb[s] + fmaf(weights[e], c, b0);
            }
        }
        if (tid == 0) g_cnt[d] = 0;   // reset for next call (first call: static zero)
        // no sync needed: next iteration touches a different row
    }
}

// ---------------------------------------------------------------------------
extern "C" void kernel_launch(void* const* d_in, const int* in_sizes, int n_in,
                              void* d_out, int out_size) {
    const int*   sources = (const int*)d_in[0];
    const int*   dests   = (const int*)d_in[1];
    const float* weights = (const float*)d_in[2];
    const float* x       = (const float*)d_in[3];
    const float* h       = (const float*)d_in[4];
    const float* W_enc   = (const float*)d_in[5];
    const float* b_enc   = (const float*)d_in[6];
    const float* W_msg   = (const float*)d_in[7];
    const float* b_msg   = (const float*)d_in[8];
    const float* W_upd   = (const float*)d_in[9];
    const float* b_upd   = (const float*)d_in[10];
    const float* W_dec   = (const float*)d_in[11];
    const float* b_dec   = (const float*)d_in[12];
    const float* W_term  = (const float*)d_in[13];
    const float* b_term  = (const float*)d_in[14];
    const float* W_pred  = (const float*)d_in[15];
    const float* b_pred  = (const float*)d_in[16];

    int E = in_sizes[0];
    int N = in_sizes[3];  // x is (N, 1)

    float* out   = (float*)d_out;
    float* out_y = out;
    float* out_p = out + N;
    float* out_h = out + N + (size_t)N * N;
    float* out_t = out_h + (size_t)N * HD;

    int EB = (E + 255) / 256;            // build blocks (thread per edge)
    int NB = (N * 32 + 255) / 256;       // encoder blocks (warp per node)

    k_build_enc<<<EB + NB, 256>>>(dests, x, h, W_enc, b_enc, W_msg, N, E, EB);
    k_update<<<NB, 256>>>(sources, weights, W_msg, b_msg, W_upd, b_upd,
                          W_dec, b_dec, W_pred, out_y, out_h, N);
    k_rowfill<<<1184, 256>>>(sources, weights, W_pred, b_pred, W_term, b_term,
                             out_p, out_t, N);
}

// round 7
// speedup vs baseline: 1.0202x; 1.0202x over previous
#include <cuda_runtime.h>
#include <math.h>
#include <stdint.h>

#define HD 32
#define MAXN 10000
#define CAP 256      // max in-degree supported (E/N = 32 mean; Poisson tail << 256)
#define FILLB 296    // fill blocks: 2/SM saturates LTS write cap, leaves slots for chain

// Scratch (device globals — no allocation allowed; zero-initialized at load)
__device__ float g_z[MAXN * HD];
__device__ float g_u[MAXN * HD];
__device__ float g_v[MAXN * HD];
__device__ float g_pa[MAXN];
__device__ float g_pb[MAXN];
__device__ float g_hsum[HD];
__device__ int   g_cnt[MAXN];     // zero at load; reset by k_update each call
__device__ int   g_list[MAXN * CAP];
__device__ int   g_upd_ticket;    // single-kernel ticket; reset by last update block

// ---------------------------------------------------------------------------
// Fill p with -1e9 using streaming stores (no L2 pollution of chain data).
// Runs on the side stream concurrently with the chain.
// ---------------------------------------------------------------------------
__global__ void __launch_bounds__(256)
k_fill(float* __restrict__ p, size_t n) {
    size_t n4 = n >> 2;
    size_t gstride = (size_t)gridDim.x * blockDim.x;
    size_t start = (size_t)blockIdx.x * blockDim.x + threadIdx.x;
    const float4 val = make_float4(-1e9f, -1e9f, -1e9f, -1e9f);
    float4* p4 = (float4*)p;
    for (size_t i = start; i < n4; i += gstride) __stcs(&p4[i], val);
    for (size_t i = (n4 << 2) + start; i < n; i += gstride) __stcs(&p[i], -1e9f);
}

// ---------------------------------------------------------------------------
// Build per-dest edge lists; block 0 also zeroes g_hsum for this call.
// ---------------------------------------------------------------------------
__global__ void k_build(const int* __restrict__ dests, int E) {
    int tid = threadIdx.x;
    if (blockIdx.x == 0 && tid < HD) g_hsum[tid] = 0.0f;
    int e = blockIdx.x * blockDim.x + tid;
    if (e >= E) return;
    int d = dests[e];
    int slot = atomicAdd(&g_cnt[d], 1);
    if (slot < CAP) g_list[d * CAP + slot] = e;
}

// ---------------------------------------------------------------------------
// Encoder: z = [x,h]@W_enc + b_enc; u = z@W_msg[0:32], v = z@W_msg[32:64].
// Warp per node, lane = feature.
// ---------------------------------------------------------------------------
__global__ void k_encoder(const float* __restrict__ x, const float* __restrict__ h,
                          const float* __restrict__ W_enc, const float* __restrict__ b_enc,
                          const float* __restrict__ W_msg, int N) {
    __shared__ float sWe[33 * HD];
    __shared__ float sWm[64 * HD];
    int tid = threadIdx.x;
    for (int i = tid; i < 33 * HD; i += blockDim.x) sWe[i] = W_enc[i];
    for (int i = tid; i < 64 * HD; i += blockDim.x) sWm[i] = W_msg[i];
    __syncthreads();

    int lane = tid & 31;
    int node = (int)((blockIdx.x * (size_t)blockDim.x + tid) >> 5);
    if (node >= N) return;

    float xn = x[node];
    float hl = h[node * HD + lane];
    float z0 = fmaf(xn, sWe[lane], b_enc[lane]);
    float z1 = 0.0f;
#pragma unroll
    for (int k = 0; k < HD; k += 2) {
        float hk0 = __shfl_sync(0xffffffffu, hl, k);
        float hk1 = __shfl_sync(0xffffffffu, hl, k + 1);
        z0 = fmaf(hk0, sWe[(1 + k) * HD + lane], z0);
        z1 = fmaf(hk1, sWe[(2 + k) * HD + lane], z1);
    }
    float z = z0 + z1;
    g_z[node * HD + lane] = z;

    float u = 0.0f, v = 0.0f;
#pragma unroll
    for (int k = 0; k < HD; k++) {
        float zk = __shfl_sync(0xffffffffu, z, k);
        u = fmaf(zk, sWm[k * HD + lane], u);
        v = fmaf(zk, sWm[(HD + k) * HD + lane], v);
    }
    g_u[node * HD + lane] = u;
    g_v[node * HD + lane] = v;
}

// ---------------------------------------------------------------------------
// Update: segment-max (atomic-free, lane-parallel edge loads, 4x-unrolled
// gathers) + decode + pred scalars + hsum. Warp per node. Last block (ticket,
// same kernel — safe) computes the termination scalar. Resets g_cnt.
// ---------------------------------------------------------------------------
__global__ void k_update(const int* __restrict__ sources, const float* __restrict__ weights,
                         const float* __restrict__ W_msg, const float* __restrict__ b_msg,
                         const float* __restrict__ W_upd, const float* __restrict__ b_upd,
                         const float* __restrict__ W_dec, const float* __restrict__ b_dec,
                         const float* __restrict__ W_pred,
                         const float* __restrict__ W_term, const float* __restrict__ b_term,
                         float* __restrict__ out_y, float* __restrict__ out_h,
                         float* __restrict__ out_t, int N) {
    __shared__ float sWu[64 * HD];
    __shared__ float red[8][HD];
    __shared__ int sIsLast;
    int tid = threadIdx.x;
    for (int i = tid; i < 64 * HD; i += blockDim.x) sWu[i] = W_upd[i];
    __syncthreads();

    int lane = tid & 31;
    int wip  = tid >> 5;
    int node = (int)((blockIdx.x * (size_t)blockDim.x + tid) >> 5);
    bool act = node < N;
    float hn = 0.0f;

    if (act) {
        float cw = W_msg[64 * HD + lane];
        int cnt = min(g_cnt[node], CAP);
        const int* lst = &g_list[node * CAP];

        float mraw = __int_as_float(0xFF800000);  // -inf
        for (int base = 0; base < cnt; base += 32) {
            int nrem = min(32, cnt - base);
            int   myS = 0;
            float myW = 0.0f;
            if (lane < nrem) {
                int e = lst[base + lane];     // coalesced
                myS = sources[e];
                myW = weights[e];
            }
            int k = 0;
            for (; k + 4 <= nrem; k += 4) {
                int   s0 = __shfl_sync(0xffffffffu, myS, k);
                int   s1 = __shfl_sync(0xffffffffu, myS, k + 1);
                int   s2 = __shfl_sync(0xffffffffu, myS, k + 2);
                int   s3 = __shfl_sync(0xffffffffu, myS, k + 3);
                float w0 = __shfl_sync(0xffffffffu, myW, k);
                float w1 = __shfl_sync(0xffffffffu, myW, k + 1);
                float w2 = __shfl_sync(0xffffffffu, myW, k + 2);
                float w3 = __shfl_sync(0xffffffffu, myW, k + 3);
                float v0 = g_v[s0 * HD + lane];   // 4 independent gathers -> MLP 4
                float v1 = g_v[s1 * HD + lane];
                float v2 = g_v[s2 * HD + lane];
                float v3 = g_v[s3 * HD + lane];
                float a = fmaxf(fmaf(w0, cw, v0), fmaf(w1, cw, v1));
                float b = fmaxf(fmaf(w2, cw, v2), fmaf(w3, cw, v3));
                mraw = fmaxf(mraw, fmaxf(a, b));
            }
            for (; k < nrem; k++) {
                int   sk = __shfl_sync(0xffffffffu, myS, k);
                float wk = __shfl_sync(0xffffffffu, myW, k);
                mraw = fmaxf(mraw, fmaf(wk, cw, g_v[sk * HD + lane]));
            }
        }

        float z = g_z[node * HD + lane];
        float m = (cnt == 0) ? 0.0f
                             : (g_u[node * HD + lane] + b_msg[lane] + mraw);

        float h0 = b_upd[lane], h1 = 0.0f;
#pragma unroll
        for (int k = 0; k < HD; k++) {
            float zk = __shfl_sync(0xffffffffu, z, k);
            float mk = __shfl_sync(0xffffffffu, m, k);
            h0 = fmaf(zk, sWu[k * HD + lane], h0);
            h1 = fmaf(mk, sWu[(HD + k) * HD + lane], h1);
        }
        hn = h0 + h1;
        out_h[node * HD + lane] = hn;

        float ry = fmaf(z, W_dec[lane], hn * W_dec[HD + lane]);
        float ra = hn * W_pred[lane];
        float rb = hn * W_pred[HD + lane];
#pragma unroll
        for (int o = 16; o > 0; o >>= 1) {
            ry += __shfl_xor_sync(0xffffffffu, ry, o);
            ra += __shfl_xor_sync(0xffffffffu, ra, o);
            rb += __shfl_xor_sync(0xffffffffu, rb, o);
        }
        if (lane == 0) {
            out_y[node] = ry + b_dec[0];
            g_pa[node] = ra;
            g_pb[node] = rb;
            g_cnt[node] = 0;   // reset for next call
        }
    }

    red[wip][lane] = act ? hn : 0.0f;
    __syncthreads();
    if (wip == 0) {
        float s = red[0][lane];
#pragma unroll
        for (int j = 1; j < 8; j++) s += red[j][lane];
        atomicAdd(&g_hsum[lane], s);
    }

    // last-block ticket (same kernel -> all blocks guaranteed to run)
    __syncthreads();
    if (tid == 0) {
        __threadfence();
        int t = atomicAdd(&g_upd_ticket, 1);
        sIsLast = (t == (int)gridDim.x - 1);
    }
    __syncthreads();
    if (sIsLast) {
        if (tid < 32) {
            float v = (__ldcg(&g_hsum[tid]) / (float)N) * W_term[tid];
#pragma unroll
            for (int o = 16; o > 0; o >>= 1) v += __shfl_xor_sync(0xffffffffu, v, o);
            if (tid == 0) {
                out_t[0] = v + b_term[0];
                g_upd_ticket = 0;   // reset for next call
            }
        }
    }
}

// ---------------------------------------------------------------------------
// Predecessor edge scores scattered into p (after fill + update). Thread/edge.
// ---------------------------------------------------------------------------
__global__ void k_pred(const int* __restrict__ dests, const int* __restrict__ sources,
                       const float* __restrict__ weights,
                       const float* __restrict__ W_pred, const float* __restrict__ b_pred,
                       float* __restrict__ p, int N, int E) {
    int e = blockIdx.x * blockDim.x + threadIdx.x;
    if (e >= E) return;
    int d = dests[e], s = sources[e];
    float sc = g_pa[d] + g_pb[s] + fmaf(weights[e], W_pred[64], b_pred[0]);
    __stcs(&p[(size_t)d * N + s], sc);
}

// ---------------------------------------------------------------------------
extern "C" void kernel_launch(void* const* d_in, const int* in_sizes, int n_in,
                              void* d_out, int out_size) {
    const int*   sources = (const int*)d_in[0];
    const int*   dests   = (const int*)d_in[1];
    const float* weights = (const float*)d_in[2];
    const float* x       = (const float*)d_in[3];
    const float* h       = (const float*)d_in[4];
    const float* W_enc   = (const float*)d_in[5];
    const float* b_enc   = (const float*)d_in[6];
    const float* W_msg   = (const float*)d_in[7];
    const float* b_msg   = (const float*)d_in[8];
    const float* W_upd   = (const float*)d_in[9];
    const float* b_upd   = (const float*)d_in[10];
    const float* W_dec   = (const float*)d_in[11];
    const float* b_dec   = (const float*)d_in[12];
    const float* W_term  = (const float*)d_in[13];
    const float* b_term  = (const float*)d_in[14];
    const float* W_pred  = (const float*)d_in[15];
    const float* b_pred  = (const float*)d_in[16];

    int E = in_sizes[0];
    int N = in_sizes[3];  // x is (N, 1)

    float* out   = (float*)d_out;
    float* out_y = out;
    float* out_p = out + N;
    float* out_h = out + N + (size_t)N * N;
    float* out_t = out_h + (size_t)N * HD;

    static cudaStream_t s_fill = nullptr;
    static cudaEvent_t ev_fork = nullptr, ev_join = nullptr;
    if (s_fill == nullptr) {
        cudaStreamCreateWithFlags(&s_fill, cudaStreamNonBlocking);
        cudaEventCreateWithFlags(&ev_fork, cudaEventDisableTiming);
        cudaEventCreateWithFlags(&ev_join, cudaEventDisableTiming);
    }

    // Fork: streaming fill on side stream (2 blocks/SM — saturates LTS writes,
    // leaves warp slots + L2 for the chain)
    cudaEventRecord(ev_fork, 0);
    cudaStreamWaitEvent(s_fill, ev_fork, 0);
    k_fill<<<FILLB, 256, 0, s_fill>>>(out_p, (size_t)N * N);
    cudaEventRecord(ev_join, s_fill);

    // Chain on main stream, co-resident with the fill
    int EB = (E + 255) / 256;
    int NB = (N * 32 + 255) / 256;
    k_build<<<EB, 256>>>(dests, E);
    k_encoder<<<NB, 256>>>(x, h, W_enc, b_enc, W_msg, N);
    k_update<<<NB, 256>>>(sources, weights, W_msg, b_msg, W_upd, b_upd,
                          W_dec, b_dec, W_pred, W_term, b_term,
                          out_y, out_h, out_t, N);

    // Join: edge-score scatter needs both the fill and g_pa/g_pb
    cudaStreamWaitEvent(0, ev_join, 0);
    k_pred<<<(E + 255) / 256, 256>>>(dests, sources, weights, W_pred, b_pred, out_p, N, E);
}

// round 9
// speedup vs baseline: 1.0836x; 1.0622x over previous
#include <cuda_runtime.h>
#include <math.h>
#include <stdint.h>

#define HD 32
#define MAXN 10000
#define CAP 256      // max in-degree supported (E/N = 32 mean; Poisson tail << 256)

// Scratch (device globals — no allocation allowed; zero-initialized at load)
__device__ float g_z[MAXN * HD];
__device__ float g_u[MAXN * HD];
__device__ float g_v[MAXN * HD];
__device__ float g_pa[MAXN];
__device__ float g_pb[MAXN];
__device__ float g_hsum[HD];
__device__ int   g_cnt[MAXN];     // zero at load; reset by k_rowfill each call
__device__ int   g_list[MAXN * CAP];
__device__ int   g_upd_ticket;    // single-kernel ticket; reset by last update block

// ---------------------------------------------------------------------------
// Build per-dest edge lists; block 0 also zeroes g_hsum for this call.
// ---------------------------------------------------------------------------
__global__ void k_build(const int* __restrict__ dests, int E) {
    int tid = threadIdx.x;
    if (blockIdx.x == 0 && tid < HD) g_hsum[tid] = 0.0f;
    int e = blockIdx.x * blockDim.x + tid;
    if (e >= E) return;
    int d = dests[e];
    int slot = atomicAdd(&g_cnt[d], 1);
    if (slot < CAP) g_list[d * CAP + slot] = e;
}

// ---------------------------------------------------------------------------
// Encoder: z = [x,h]@W_enc + b_enc; u = z@W_msg[0:32], v = z@W_msg[32:64].
// Warp per node, lane = feature.
// ---------------------------------------------------------------------------
__global__ void k_encoder(const float* __restrict__ x, const float* __restrict__ h,
                          const float* __restrict__ W_enc, const float* __restrict__ b_enc,
                          const float* __restrict__ W_msg, int N) {
    __shared__ float sWe[33 * HD];
    __shared__ float sWm[64 * HD];
    int tid = threadIdx.x;
    for (int i = tid; i < 33 * HD; i += blockDim.x) sWe[i] = W_enc[i];
    for (int i = tid; i < 64 * HD; i += blockDim.x) sWm[i] = W_msg[i];
    __syncthreads();

    int lane = tid & 31;
    int node = (int)((blockIdx.x * (size_t)blockDim.x + tid) >> 5);
    if (node >= N) return;

    float xn = x[node];
    float hl = h[node * HD + lane];
    float z0 = fmaf(xn, sWe[lane], b_enc[lane]);
    float z1 = 0.0f;
#pragma unroll
    for (int k = 0; k < HD; k += 2) {
        float hk0 = __shfl_sync(0xffffffffu, hl, k);
        float hk1 = __shfl_sync(0xffffffffu, hl, k + 1);
        z0 = fmaf(hk0, sWe[(1 + k) * HD + lane], z0);
        z1 = fmaf(hk1, sWe[(2 + k) * HD + lane], z1);
    }
    float z = z0 + z1;
    g_z[node * HD + lane] = z;

    float u = 0.0f, v = 0.0f;
#pragma unroll
    for (int k = 0; k < HD; k++) {
        float zk = __shfl_sync(0xffffffffu, z, k);
        u = fmaf(zk, sWm[k * HD + lane], u);
        v = fmaf(zk, sWm[(HD + k) * HD + lane], v);
    }
    g_u[node * HD + lane] = u;
    g_v[node * HD + lane] = v;
}

// ---------------------------------------------------------------------------
// Update: segment-max (atomic-free, lane-parallel edge loads, 4x-unrolled
// gathers) + decode + pred scalars + hsum. Warp per node. Last block (ticket,
// same kernel — safe) computes the termination scalar.
// ---------------------------------------------------------------------------
__global__ void k_update(const int* __restrict__ sources, const float* __restrict__ weights,
                         const float* __restrict__ W_msg, const float* __restrict__ b_msg,
                         const float* __restrict__ W_upd, const float* __restrict__ b_upd,
                         const float* __restrict__ W_dec, const float* __restrict__ b_dec,
                         const float* __restrict__ W_pred,
                         const float* __restrict__ W_term, const float* __restrict__ b_term,
                         float* __restrict__ out_y, float* __restrict__ out_h,
                         float* __restrict__ out_t, int N) {
    __shared__ float sWu[64 * HD];
    __shared__ float red[8][HD];
    __shared__ int sIsLast;
    int tid = threadIdx.x;
    for (int i = tid; i < 64 * HD; i += blockDim.x) sWu[i] = W_upd[i];
    __syncthreads();

    int lane = tid & 31;
    int wip  = tid >> 5;
    int node = (int)((blockIdx.x * (size_t)blockDim.x + tid) >> 5);
    bool act = node < N;
    float hn = 0.0f;

    if (act) {
        float cw = W_msg[64 * HD + lane];
        int cnt = min(g_cnt[node], CAP);
        const int* lst = &g_list[node * CAP];

        float mraw = __int_as_float(0xFF800000);  // -inf
        for (int base = 0; base < cnt; base += 32) {
            int nrem = min(32, cnt - base);
            int   myS = 0;
            float myW = 0.0f;
            if (lane < nrem) {
                int e = lst[base + lane];     // coalesced
                myS = sources[e];
                myW = weights[e];
            }
            int k = 0;
            for (; k + 4 <= nrem; k += 4) {
                int   s0 = __shfl_sync(0xffffffffu, myS, k);
                int   s1 = __shfl_sync(0xffffffffu, myS, k + 1);
                int   s2 = __shfl_sync(0xffffffffu, myS, k + 2);
                int   s3 = __shfl_sync(0xffffffffu, myS, k + 3);
                float w0 = __shfl_sync(0xffffffffu, myW, k);
                float w1 = __shfl_sync(0xffffffffu, myW, k + 1);
                float w2 = __shfl_sync(0xffffffffu, myW, k + 2);
                float w3 = __shfl_sync(0xffffffffu, myW, k + 3);
                float v0 = g_v[s0 * HD + lane];   // 4 independent gathers -> MLP 4
                float v1 = g_v[s1 * HD + lane];
                float v2 = g_v[s2 * HD + lane];
                float v3 = g_v[s3 * HD + lane];
                float a = fmaxf(fmaf(w0, cw, v0), fmaf(w1, cw, v1));
                float b = fmaxf(fmaf(w2, cw, v2), fmaf(w3, cw, v3));
                mraw = fmaxf(mraw, fmaxf(a, b));
            }
            for (; k < nrem; k++) {
                int   sk = __shfl_sync(0xffffffffu, myS, k);
                float wk = __shfl_sync(0xffffffffu, myW, k);
                mraw = fmaxf(mraw, fmaf(wk, cw, g_v[sk * HD + lane]));
            }
        }

        float z = g_z[node * HD + lane];
        float m = (cnt == 0) ? 0.0f
                             : (g_u[node * HD + lane] + b_msg[lane] + mraw);

        float h0 = b_upd[lane], h1 = 0.0f;
#pragma unroll
        for (int k = 0; k < HD; k++) {
            float zk = __shfl_sync(0xffffffffu, z, k);
            float mk = __shfl_sync(0xffffffffu, m, k);
            h0 = fmaf(zk, sWu[k * HD + lane], h0);
            h1 = fmaf(mk, sWu[(HD + k) * HD + lane], h1);
        }
        hn = h0 + h1;
        out_h[node * HD + lane] = hn;

        float ry = fmaf(z, W_dec[lane], hn * W_dec[HD + lane]);
        float ra = hn * W_pred[lane];
        float rb = hn * W_pred[HD + lane];
#pragma unroll
        for (int o = 16; o > 0; o >>= 1) {
            ry += __shfl_xor_sync(0xffffffffu, ry, o);
            ra += __shfl_xor_sync(0xffffffffu, ra, o);
            rb += __shfl_xor_sync(0xffffffffu, rb, o);
        }
        if (lane == 0) {
            out_y[node] = ry + b_dec[0];
            g_pa[node] = ra;
            g_pb[node] = rb;
        }
    }

    red[wip][lane] = act ? hn : 0.0f;
    __syncthreads();
    if (wip == 0) {
        float s = red[0][lane];
#pragma unroll
        for (int j = 1; j < 8; j++) s += red[j][lane];
        atomicAdd(&g_hsum[lane], s);
    }

    // last-block ticket (same kernel -> all blocks guaranteed to run)
    __syncthreads();
    if (tid == 0) {
        __threadfence();
        int t = atomicAdd(&g_upd_ticket, 1);
        sIsLast = (t == (int)gridDim.x - 1);
    }
    __syncthreads();
    if (sIsLast) {
        if (tid < 32) {
            float v = (__ldcg(&g_hsum[tid]) / (float)N) * W_term[tid];
#pragma unroll
            for (int o = 16; o > 0; o >>= 1) v += __shfl_xor_sync(0xffffffffu, v, o);
            if (tid == 0) {
                out_t[0] = v + b_term[0];
                g_upd_ticket = 0;   // reset for next call
            }
        }
    }
}

// ---------------------------------------------------------------------------
// Fused row fill + edge-score overwrite: one block per row of p. Each row is
// written exactly once (streaming stores). Resets g_cnt for the next replay.
// ---------------------------------------------------------------------------
__global__ void __launch_bounds__(256)
k_rowfill(const int* __restrict__ sources, const float* __restrict__ weights,
          const float* __restrict__ W_pred, const float* __restrict__ b_pred,
          float* __restrict__ p, int N) {
    int d = blockIdx.x;
    int tid = threadIdx.x;
    float* row = p + (size_t)d * N;
    int n4 = N >> 2;
    const float4 val = make_float4(-1e9f, -1e9f, -1e9f, -1e9f);
    float4* row4 = (float4*)row;
    for (int i = tid; i < n4; i += blockDim.x) __stcs(&row4[i], val);
    for (int i = (n4 << 2) + tid; i < N; i += blockDim.x) __stcs(&row[i], -1e9f);
    __syncthreads();   // row fully filled before edge overwrites

    int cnt = min(g_cnt[d], CAP);
    if (tid < cnt) {
        float pa = g_pa[d];
        float c  = W_pred[64];
        float b0 = b_pred[0];
        for (int i = tid; i < cnt; i += blockDim.x) {
            int e = g_list[d * CAP + i];
            int s = sources[e];
            row[s] = pa + g_pb[s] + fmaf(weights[e], c, b0);
        }
    }
    if (tid == 0) g_cnt[d] = 0;   // reset for next call
}

// ---------------------------------------------------------------------------
extern "C" void kernel_launch(void* const* d_in, const int* in_sizes, int n_in,
                              void* d_out, int out_size) {
    const int*   sources = (const int*)d_in[0];
    const int*   dests   = (const int*)d_in[1];
    const float* weights = (const float*)d_in[2];
    const float* x       = (const float*)d_in[3];
    const float* h       = (const float*)d_in[4];
    const float* W_enc   = (const float*)d_in[5];
    const float* b_enc   = (const float*)d_in[6];
    const float* W_msg   = (const float*)d_in[7];
    const float* b_msg   = (const float*)d_in[8];
    const float* W_upd   = (const float*)d_in[9];
    const float* b_upd   = (const float*)d_in[10];
    const float* W_dec   = (const float*)d_in[11];
    const float* b_dec   = (const float*)d_in[12];
    const float* W_term  = (const float*)d_in[13];
    const float* b_term  = (const float*)d_in[14];
    const float* W_pred  = (const float*)d_in[15];
    const float* b_pred  = (const float*)d_in[16];

    int E = in_sizes[0];
    int N = in_sizes[3];  // x is (N, 1)

    float* out   = (float*)d_out;
    float* out_y = out;
    float* out_p = out + N;
    float* out_h = out + N + (size_t)N * N;
    float* out_t = out_h + (size_t)N * HD;

    int EB = (E + 255) / 256;
    int NB = (N * 32 + 255) / 256;

    k_build<<<EB, 256>>>(dests, E);
    k_encoder<<<NB, 256>>>(x, h, W_enc, b_enc, W_msg, N);
    k_update<<<NB, 256>>>(sources, weights, W_msg, b_msg, W_upd, b_upd,
                          W_dec, b_dec, W_pred, W_term, b_term,
                          out_y, out_h, out_t, N);
    k_rowfill<<<N, 256>>>(sources, weights, W_pred, b_pred, out_p, N);
}